// round 9
// baseline (speedup 1.0000x reference)
#include <cuda_runtime.h>
#include <cstdint>

#define VOCAB  50000
#define EMBED  256
#define MAXLEN 512
#define UNITS  32
#define F1     16
#define BATCH  512
#define PHASE  256     // steps staged per SMEM refill

// Scratch: projected embedding table P[v][u] = sum_e emb[v][e]*Wx[e][u], prescaled
// by 2*log2(e) so the recurrence can feed ex2 directly.
__device__ float g_P[VOCAB * UNITS];

#define TANH_SCALE 2.8853900817779268f   // 2*log2(e)

// Dynamic SMEM layout (per block of 4 warps):
//   [0, 131072)        sXW : 4 warps x PHASE x 32 floats (staged xw rows)
//   [131072, 139264)   sTok: 4 x MAXLEN ints
//   [139264, 139776)   sR  : 4 x 32 floats (broadcast rows, 128B each)
#define SMEM_XW   0
#define SMEM_TOK  131072
#define SMEM_R    139264
#define SMEM_TOTAL 139776

// ---------------------------------------------------------------------------
// Packed f32x2 helpers
// ---------------------------------------------------------------------------
__device__ __forceinline__ unsigned long long pk2(float lo, float hi) {
    unsigned long long r;
    asm("mov.b64 %0, {%1, %2};" : "=l"(r) : "f"(lo), "f"(hi));
    return r;
}
__device__ __forceinline__ void upk2(float& lo, float& hi, unsigned long long v) {
    asm("mov.b64 {%0, %1}, %2;" : "=f"(lo), "=f"(hi) : "l"(v));
}
__device__ __forceinline__ unsigned long long fma2(
    unsigned long long a, unsigned long long b, unsigned long long c) {
    unsigned long long d;
    asm("fma.rn.f32x2 %0, %1, %2, %3;" : "=l"(d) : "l"(a), "l"(b), "l"(c));
    return d;
}
__device__ __forceinline__ unsigned long long mul2(
    unsigned long long a, unsigned long long b) {
    unsigned long long d;
    asm("mul.rn.f32x2 %0, %1, %2;" : "=l"(d) : "l"(a), "l"(b));
    return d;
}
__device__ __forceinline__ unsigned long long add2(
    unsigned long long a, unsigned long long b) {
    unsigned long long d;
    asm("add.rn.f32x2 %0, %1, %2;" : "=l"(d) : "l"(a), "l"(b));
    return d;
}

// ---------------------------------------------------------------------------
// Kernel A: P = (emb_table @ Wx) * TANH_SCALE  (R1 scalar version, ~13us,
// near the fp32 FMA-issue floor for 0.82 GFLOP; not the bottleneck)
// ---------------------------------------------------------------------------
__global__ void __launch_bounds__(128) proj_kernel(
    const float* __restrict__ emb, const float* __restrict__ Wx)
{
    __shared__ float sW[EMBED * UNITS];
    const int t = threadIdx.x;
    for (int i = t; i < EMBED * UNITS / 4; i += 128)
        ((float4*)sW)[i] = ((const float4*)Wx)[i];
    __syncthreads();

    const int ug    = t & 3;
    const int s     = t >> 2;
    const int rbase = blockIdx.x * 128 + s * 4;

    float acc[4][8];
    #pragma unroll
    for (int rr = 0; rr < 4; rr++)
        #pragma unroll
        for (int j = 0; j < 8; j++) acc[rr][j] = 0.f;

    const float* arow[4];
    #pragma unroll
    for (int rr = 0; rr < 4; rr++) {
        int r = rbase + rr;
        if (r >= VOCAB) r = VOCAB - 1;
        arow[rr] = emb + (size_t)r * EMBED;
    }

    for (int e0 = 0; e0 < EMBED; e0 += 4) {
        float4 av[4];
        #pragma unroll
        for (int rr = 0; rr < 4; rr++)
            av[rr] = *(const float4*)(arow[rr] + e0);

        #pragma unroll
        for (int ee = 0; ee < 4; ee++) {
            const float4 w0 = *(const float4*)&sW[(e0 + ee) * UNITS + ug * 8];
            const float4 w1 = *(const float4*)&sW[(e0 + ee) * UNITS + ug * 8 + 4];
            #pragma unroll
            for (int rr = 0; rr < 4; rr++) {
                const float a = ((const float*)&av[rr])[ee];
                acc[rr][0] = fmaf(a, w0.x, acc[rr][0]);
                acc[rr][1] = fmaf(a, w0.y, acc[rr][1]);
                acc[rr][2] = fmaf(a, w0.z, acc[rr][2]);
                acc[rr][3] = fmaf(a, w0.w, acc[rr][3]);
                acc[rr][4] = fmaf(a, w1.x, acc[rr][4]);
                acc[rr][5] = fmaf(a, w1.y, acc[rr][5]);
                acc[rr][6] = fmaf(a, w1.z, acc[rr][6]);
                acc[rr][7] = fmaf(a, w1.w, acc[rr][7]);
            }
        }
    }

    #pragma unroll
    for (int rr = 0; rr < 4; rr++) {
        const int r = rbase + rr;
        if (r < VOCAB) {
            float4 o0, o1;
            o0.x = acc[rr][0] * TANH_SCALE; o0.y = acc[rr][1] * TANH_SCALE;
            o0.z = acc[rr][2] * TANH_SCALE; o0.w = acc[rr][3] * TANH_SCALE;
            o1.x = acc[rr][4] * TANH_SCALE; o1.y = acc[rr][5] * TANH_SCALE;
            o1.z = acc[rr][6] * TANH_SCALE; o1.w = acc[rr][7] * TANH_SCALE;
            *(float4*)&g_P[r * UNITS + ug * 8]     = o0;
            *(float4*)&g_P[r * UNITS + ug * 8 + 4] = o1;
        }
    }
}

// ---------------------------------------------------------------------------
// Kernel B: recurrence + head. One warp per batch row, lane u owns unit u.
// State r = 1/(1+e^(2x)) (h = 1-2r); affine folded into weights.
// The xw sequence is PRE-STAGED into SMEM in two 256-step phases, so the
// step loop contains only: 1 LDS.32 seed-prefetch + STS + syncwarp +
// 8 LDS.128 broadcast + 16 packed MACs + packed tree + ex2/rcp. No LDGs,
// no token reads, no ping-pong machinery inside the recurrence.
// ---------------------------------------------------------------------------
__global__ void __launch_bounds__(128, 1) rnn_kernel(
    const int*   __restrict__ tokens,
    const float* __restrict__ Wh,
    const float* __restrict__ bvec,
    const float* __restrict__ W1,
    const float* __restrict__ b1,
    const float* __restrict__ W2,
    const float* __restrict__ b2,
    float*       __restrict__ out)
{
    extern __shared__ char dsm[];
    float* sXW  = (float*)(dsm + SMEM_XW);
    int*   sTok = (int*)  (dsm + SMEM_TOK);
    float* sR   = (float*)(dsm + SMEM_R);

    const int tid  = threadIdx.x;
    const int wid  = tid >> 5;
    const int lane = tid & 31;
    const int b0   = blockIdx.x * 4;

    for (int i = tid; i < 4 * MAXLEN; i += 128)
        sTok[i] = tokens[b0 * MAXLEN + i];
    __syncthreads();

    const int* myTok = sTok + wid * MAXLEN;
    float*     myXW  = sXW + wid * (PHASE * UNITS);
    float*     sRrow = sR + wid * UNITS;
    const int  brow  = b0 + wid;

    // Packed column weights: wpk[k] = {-2S*Wh[2k][lane], -2S*Wh[2k+1][lane]}
    unsigned long long wpk[16];
    float cs = 0.f;
    #pragma unroll
    for (int v = 0; v < 32; v += 2) {
        const float w0 = Wh[v * UNITS + lane];
        const float w1 = Wh[(v + 1) * UNITS + lane];
        cs += w0 + w1;
        wpk[v >> 1] = pk2(w0 * (-2.0f * TANH_SCALE), w1 * (-2.0f * TANH_SCALE));
    }
    const float cbias = (bvec[lane] + cs) * TANH_SCALE;

    const ulonglong2* rrow = (const ulonglong2*)sRrow;   // 8 x 16B
    const float*      xp   = myXW + lane;

    float r = 0.5f;                         // h = 1 - 2r = 0
    for (int p = 0; p < 2; p++) {
        // ---- Stage this phase's xw rows: 256 gathers, MLP-8 pipelined ----
        const int4* tokp4 = (const int4*)(myTok + p * PHASE);
        #pragma unroll 4
        for (int t8 = 0; t8 < PHASE / 8; t8++) {
            const int4 ta = tokp4[2 * t8];
            const int4 tb = tokp4[2 * t8 + 1];
            const float v0 = g_P[ta.x * UNITS + lane];
            const float v1 = g_P[ta.y * UNITS + lane];
            const float v2 = g_P[ta.z * UNITS + lane];
            const float v3 = g_P[ta.w * UNITS + lane];
            const float v4 = g_P[tb.x * UNITS + lane];
            const float v5 = g_P[tb.y * UNITS + lane];
            const float v6 = g_P[tb.z * UNITS + lane];
            const float v7 = g_P[tb.w * UNITS + lane];
            float* dst = myXW + (8 * t8) * UNITS + lane;
            dst[0 * UNITS] = v0; dst[1 * UNITS] = v1;
            dst[2 * UNITS] = v2; dst[3 * UNITS] = v3;
            dst[4 * UNITS] = v4; dst[5 * UNITS] = v5;
            dst[6 * UNITS] = v6; dst[7 * UNITS] = v7;
        }
        __syncwarp();

        // ---- Run 256 recurrence steps off SMEM only ----
        float seedN = xp[0] + cbias;
        #pragma unroll 4
        for (int t = 0; t < PHASE; t++) {
            const float seed = seedN;
            const int tn = (t + 1 < PHASE) ? (t + 1) : t;   // clamp, off-path
            seedN = xp[tn * UNITS] + cbias;                  // prefetch next

            sRrow[lane] = r;
            __syncwarp();

            const ulonglong2 q0 = rrow[0];
            const ulonglong2 q1 = rrow[1];
            const ulonglong2 q2 = rrow[2];
            const ulonglong2 q3 = rrow[3];
            const ulonglong2 q4 = rrow[4];
            const ulonglong2 q5 = rrow[5];
            const ulonglong2 q6 = rrow[6];
            const ulonglong2 q7 = rrow[7];

            unsigned long long a0 = fma2(q0.x, wpk[0], pk2(seed, 0.f));
            unsigned long long a1 = mul2(q1.x, wpk[2]);
            unsigned long long a2 = mul2(q2.x, wpk[4]);
            unsigned long long a3 = mul2(q3.x, wpk[6]);
            unsigned long long a4 = mul2(q4.x, wpk[8]);
            unsigned long long a5 = mul2(q5.x, wpk[10]);
            unsigned long long a6 = mul2(q6.x, wpk[12]);
            unsigned long long a7 = mul2(q7.x, wpk[14]);
            a0 = fma2(q0.y, wpk[1],  a0);
            a1 = fma2(q1.y, wpk[3],  a1);
            a2 = fma2(q2.y, wpk[5],  a2);
            a3 = fma2(q3.y, wpk[7],  a3);
            a4 = fma2(q4.y, wpk[9],  a4);
            a5 = fma2(q5.y, wpk[11], a5);
            a6 = fma2(q6.y, wpk[13], a6);
            a7 = fma2(q7.y, wpk[15], a7);

            const unsigned long long s0 = add2(a0, a1);
            const unsigned long long s1 = add2(a2, a3);
            const unsigned long long s2 = add2(a4, a5);
            const unsigned long long s3 = add2(a6, a7);
            const unsigned long long t1 = add2(s0, s1);
            const unsigned long long t2 = add2(s2, s3);
            const unsigned long long u  = add2(t1, t2);
            float lo, hi;
            upk2(lo, hi, u);
            const float z2 = lo + hi;       // = 2*log2(e) * preact
            float e, rn;
            asm("ex2.approx.f32 %0, %1;" : "=f"(e) : "f"(z2));
            asm("rcp.approx.f32 %0, %1;" : "=f"(rn) : "f"(e + 1.0f));
            r = rn;
        }
    }

    const float h = fmaf(-2.0f, r, 1.0f);   // final hidden value for lane

    // Head: f = h@W1 + b1 (16), z = f@W2 + b2, out = sigmoid(z)  (one-time)
    float facc = 0.f;
    #pragma unroll
    for (int v = 0; v < 32; v++) {
        const float hv = __shfl_sync(0xffffffffu, h, v);
        if (lane < F1)
            facc = fmaf(hv, W1[v * F1 + lane], facc);
    }
    float p = 0.f;
    if (lane < F1) p = (facc + b1[lane]) * W2[lane];
    #pragma unroll
    for (int off = 16; off > 0; off >>= 1)
        p += __shfl_xor_sync(0xffffffffu, p, off);

    if (lane == 0) {
        const float z = p + b2[0];
        float e, rr;
        asm("ex2.approx.f32 %0, %1;" : "=f"(e) : "f"(-z * 1.4426950408889634f));
        asm("rcp.approx.f32 %0, %1;" : "=f"(rr) : "f"(1.0f + e));
        out[brow] = rr;
    }
}

// ---------------------------------------------------------------------------
extern "C" void kernel_launch(void* const* d_in, const int* in_sizes, int n_in,
                              void* d_out, int out_size)
{
    const int*   tokens = (const int*)  d_in[0];
    const float* emb    = (const float*)d_in[1];
    const float* Wx     = (const float*)d_in[2];
    const float* Wh     = (const float*)d_in[3];
    const float* b      = (const float*)d_in[4];
    const float* W1     = (const float*)d_in[5];
    const float* b1     = (const float*)d_in[6];
    const float* W2     = (const float*)d_in[7];
    const float* b2     = (const float*)d_in[8];
    float* out = (float*)d_out;

    // Opt-in to >48KB dynamic SMEM (host attribute set; idempotent, not a
    // stream op, graph-capture safe).
    static int attr_done = 0;
    if (!attr_done) {
        cudaFuncSetAttribute(rnn_kernel,
                             cudaFuncAttributeMaxDynamicSharedMemorySize,
                             SMEM_TOTAL);
        attr_done = 1;
    }

    proj_kernel<<<(VOCAB + 127) / 128, 128>>>(emb, Wx);
    rnn_kernel<<<BATCH / 4, 128, SMEM_TOTAL>>>(tokens, Wh, b, W1, b1, W2, b2, out);
}